// round 2
// baseline (speedup 1.0000x reference)
#include <cuda_runtime.h>
#include <cuda_bf16.h>
#include <math.h>

// Problem constants (fixed by the dataset)
#define NN 50000
#define EE 800000
#define HH 128
#define FIN 128
#define NSE 16
#define LL 3
#define CC 10
#define GG 256

// ---------------- scratch (static __device__ — no allocs allowed) ----------
__device__ float d_x [NN * HH];       // x stream
__device__ float d_s [NN * HH];       // s stream
__device__ float d_h [NN * 2 * HH];   // concat / GIN agg result
__device__ float d_h1[NN * HH];       // GIN intermediate / whp out
__device__ float d_hs[NN * HH];       // s @ gcn_w
__device__ float d_g [GG * HH];       // pooled
__device__ float d_gp[GG * HH];       // post out
__device__ float d_dinv[NN];
__device__ int   d_degc[NN];
__device__ int   d_rowptr[NN + 1];
__device__ int   d_cursor[NN];
__device__ int   d_col[EE];

// ---------------- CSR build ------------------------------------------------
__global__ void count_deg_kernel(const int* __restrict__ ei, int* __restrict__ degc) {
    int e = blockIdx.x * blockDim.x + threadIdx.x;
    if (e < EE) {
        int dst = ei[EE + e];
        atomicAdd(&degc[dst], 1);
    }
}

// single block, 1024 threads: exclusive scan of degc -> rowptr, plus dinv
__global__ void scan_deg_kernel(const int* __restrict__ degc,
                                int* __restrict__ rowptr,
                                float* __restrict__ dinv) {
    __shared__ int ssum[1024];
    int t = threadIdx.x;
    const int chunk = (NN + 1023) / 1024;
    int b0 = t * chunk;
    int b1 = b0 + chunk; if (b1 > NN) b1 = NN;
    int sum = 0;
    for (int i = b0; i < b1; i++) sum += degc[i];
    ssum[t] = sum;
    __syncthreads();
    // inclusive Hillis-Steele scan over 1024 partials
    for (int off = 1; off < 1024; off <<= 1) {
        int v = 0;
        if (t >= off) v = ssum[t - off];
        __syncthreads();
        if (t >= off) ssum[t] += v;
        __syncthreads();
    }
    int prefix = (t == 0) ? 0 : ssum[t - 1];
    for (int i = b0; i < b1; i++) {
        int d = degc[i];
        rowptr[i] = prefix;
        prefix += d;
        dinv[i] = rsqrtf((float)d + 1.0f);
    }
    if (t == 1023) rowptr[NN] = ssum[1023];
}

__global__ void fill_csr_kernel(const int* __restrict__ ei,
                                const int* __restrict__ rowptr,
                                int* __restrict__ cursor,
                                int* __restrict__ col) {
    int e = blockIdx.x * blockDim.x + threadIdx.x;
    if (e < EE) {
        int src = ei[e];
        int dst = ei[EE + e];
        int pos = atomicAdd(&cursor[dst], 1);
        col[rowptr[dst] + pos] = src;
    }
}

// ---------------- SGEMM: C[M,128] = A[M,K] @ W[K,128] (+bias)(+relu) -------
// Classic 128x128 block, BK=8, 8x8 per-thread microtile, 256 threads.
#define BM 128
#define BN 128
#define BK 8
__global__ __launch_bounds__(256)
void sgemm_kernel(const float* __restrict__ A, const float* __restrict__ W,
                  const float* __restrict__ bias, float* __restrict__ C,
                  int M, int K, int relu) {
    __shared__ float As[BK][BM];
    __shared__ float Bs[BK][BN];
    const int row0 = blockIdx.x * BM;
    const int tid  = threadIdx.x;
    const int ty   = tid >> 4;     // 0..15
    const int tx   = tid & 15;     // 0..15

    float acc[8][8];
#pragma unroll
    for (int i = 0; i < 8; i++)
#pragma unroll
        for (int j = 0; j < 8; j++) acc[i][j] = 0.0f;

    const int aRow = tid >> 1;           // 0..127
    const int aK   = (tid & 1) * 4;      // 0 or 4
    const int bRow = tid >> 5;           // 0..7
    const int bCol = (tid & 31) * 4;     // 0..124

    for (int k0 = 0; k0 < K; k0 += BK) {
        float4 av = make_float4(0.f, 0.f, 0.f, 0.f);
        if (row0 + aRow < M)
            av = *(const float4*)(A + (size_t)(row0 + aRow) * K + k0 + aK);
        As[aK + 0][aRow] = av.x;
        As[aK + 1][aRow] = av.y;
        As[aK + 2][aRow] = av.z;
        As[aK + 3][aRow] = av.w;

        float4 bv = *(const float4*)(W + (size_t)(k0 + bRow) * BN + bCol);
        *(float4*)&Bs[bRow][bCol] = bv;
        __syncthreads();

#pragma unroll
        for (int kk = 0; kk < BK; kk++) {
            float4 a0 = *(float4*)&As[kk][ty * 8];
            float4 a1 = *(float4*)&As[kk][ty * 8 + 4];
            float4 b0 = *(float4*)&Bs[kk][tx * 8];
            float4 b1 = *(float4*)&Bs[kk][tx * 8 + 4];
            float ra[8] = {a0.x, a0.y, a0.z, a0.w, a1.x, a1.y, a1.z, a1.w};
            float rb[8] = {b0.x, b0.y, b0.z, b0.w, b1.x, b1.y, b1.z, b1.w};
#pragma unroll
            for (int i = 0; i < 8; i++)
#pragma unroll
                for (int j = 0; j < 8; j++)
                    acc[i][j] = fmaf(ra[i], rb[j], acc[i][j]);
        }
        __syncthreads();
    }

#pragma unroll
    for (int i = 0; i < 8; i++) {
        int row = row0 + ty * 8 + i;
        if (row < M) {
#pragma unroll
            for (int j = 0; j < 8; j++) {
                int colc = tx * 8 + j;
                float v = acc[i][j];
                if (bias) v += bias[colc];
                if (relu) v = fmaxf(v, 0.0f);
                C[(size_t)row * BN + colc] = v;
            }
        }
    }
}

// ---------------- GIN aggregation: h[i,:] = base[i,:] + sum_in base[src,:] -
// base = concat(x, s). One block (256 thr) per destination node.
__global__ void gin_agg_kernel(const float* __restrict__ x,
                               const float* __restrict__ s,
                               const int* __restrict__ col,
                               const int* __restrict__ rowptr,
                               float* __restrict__ h) {
    int i = blockIdx.x;
    int f = threadIdx.x;                 // 0..255
    const float* base = (f < HH) ? x : s;
    int fo = (f < HH) ? f : f - HH;
    float acc = base[(size_t)i * HH + fo];
    int b = rowptr[i], e = rowptr[i + 1];
    for (int j = b; j < e; j++) {
        int src = col[j];
        acc += base[(size_t)src * HH + fo];
    }
    h[(size_t)i * (2 * HH) + f] = acc;
}

// ---------------- GCN aggregation: s = tanh(dinv_i*sum dinv_j*hs_j + hs_i*dinv_i^2 + b)
__global__ void gcn_agg_kernel(const float* __restrict__ hs,
                               const float* __restrict__ dinv,
                               const int* __restrict__ col,
                               const int* __restrict__ rowptr,
                               const float* __restrict__ bias,
                               float* __restrict__ s) {
    int i = blockIdx.x;
    int f = threadIdx.x;                 // 0..127
    float acc = 0.0f;
    int b = rowptr[i], e = rowptr[i + 1];
    for (int j = b; j < e; j++) {
        int src = col[j];
        acc = fmaf(dinv[src], hs[(size_t)src * HH + f], acc);
    }
    float di = dinv[i];
    float v = di * acc + hs[(size_t)i * HH + f] * di * di + bias[f];
    s[(size_t)i * HH + f] = tanhf(v);
}

// ---------------- concat [x|s] -> h --------------------------------------
__global__ void concat_kernel(const float* __restrict__ x,
                              const float* __restrict__ s,
                              float* __restrict__ h) {
    int idx = blockIdx.x * blockDim.x + threadIdx.x;   // N*64 float4 slots
    if (idx < NN * 64) {
        int i = idx >> 6;
        int q = idx & 63;
        float4 v = (q < 32) ? ((const float4*)x)[(size_t)i * 32 + q]
                            : ((const float4*)s)[(size_t)i * 32 + q - 32];
        ((float4*)h)[idx] = v;
    }
}

// ---------------- global add pool -----------------------------------------
__global__ void pool_kernel(const float* __restrict__ xf,
                            const int* __restrict__ batch,
                            float* __restrict__ g) {
    int idx = blockIdx.x * blockDim.x + threadIdx.x;   // N*H
    if (idx < NN * HH) {
        int i = idx >> 7;
        int f = idx & 127;
        atomicAdd(&g[batch[i] * HH + f], xf[idx]);
    }
}

// ---------------- post: relu(g @ post_w + b) ------------------------------
__global__ void post_kernel(const float* __restrict__ g,
                            const float* __restrict__ W,
                            const float* __restrict__ bias,
                            float* __restrict__ gp) {
    int r = blockIdx.x;       // 0..255
    int c = threadIdx.x;      // 0..127
    __shared__ float row[HH];
    row[c] = g[(size_t)r * HH + c];
    __syncthreads();
    float acc = bias[c];
#pragma unroll 8
    for (int k = 0; k < HH; k++) acc = fmaf(row[k], W[(size_t)k * HH + c], acc);
    gp[(size_t)r * HH + c] = fmaxf(acc, 0.0f);
}

// ---------------- readout + log_softmax ----------------------------------
__global__ void readout_kernel(const float* __restrict__ gp,
                               const float* __restrict__ W,
                               const float* __restrict__ bias,
                               float* __restrict__ out) {
    int r = blockIdx.x * blockDim.x + threadIdx.x;
    if (r < GG) {
        float logit[CC];
#pragma unroll
        for (int c = 0; c < CC; c++) logit[c] = bias[c];
        for (int k = 0; k < HH; k++) {
            float gv = gp[(size_t)r * HH + k];
#pragma unroll
            for (int c = 0; c < CC; c++)
                logit[c] = fmaf(gv, W[(size_t)k * CC + c], logit[c]);
        }
        float m = logit[0];
#pragma unroll
        for (int c = 1; c < CC; c++) m = fmaxf(m, logit[c]);
        float sum = 0.0f;
#pragma unroll
        for (int c = 0; c < CC; c++) sum += expf(logit[c] - m);
        float lse = m + logf(sum);
#pragma unroll
        for (int c = 0; c < CC; c++) out[(size_t)r * CC + c] = logit[c] - lse;
    }
}

// ---------------- driver ---------------------------------------------------
extern "C" void kernel_launch(void* const* d_in, const int* in_sizes, int n_in,
                              void* d_out, int out_size) {
    const float* x_in   = (const float*)d_in[0];
    const float* s_in   = (const float*)d_in[1];
    const int*   ei     = (const int*)d_in[2];
    const int*   batch  = (const int*)d_in[3];
    const float* pre_w  = (const float*)d_in[4];
    const float* pre_b  = (const float*)d_in[5];
    const float* emb_w  = (const float*)d_in[6];
    const float* emb_b  = (const float*)d_in[7];
    const float* gin_w1 = (const float*)d_in[8];
    const float* gin_b1 = (const float*)d_in[9];
    const float* gin_w2 = (const float*)d_in[10];
    const float* gin_b2 = (const float*)d_in[11];
    const float* gcn_w  = (const float*)d_in[12];
    const float* gcn_b  = (const float*)d_in[13];
    const float* whp_w  = (const float*)d_in[14];
    const float* whp_b  = (const float*)d_in[15];
    const float* post_w = (const float*)d_in[16];
    const float* post_b = (const float*)d_in[17];
    const float* ro_w   = (const float*)d_in[18];
    const float* ro_b   = (const float*)d_in[19];
    float* out = (float*)d_out;

    float *px, *ps, *ph, *ph1, *phs, *pg, *pgp, *pdinv;
    int *pdegc, *prow, *pcur, *pcol;
    cudaGetSymbolAddress((void**)&px,    d_x);
    cudaGetSymbolAddress((void**)&ps,    d_s);
    cudaGetSymbolAddress((void**)&ph,    d_h);
    cudaGetSymbolAddress((void**)&ph1,   d_h1);
    cudaGetSymbolAddress((void**)&phs,   d_hs);
    cudaGetSymbolAddress((void**)&pg,    d_g);
    cudaGetSymbolAddress((void**)&pgp,   d_gp);
    cudaGetSymbolAddress((void**)&pdinv, d_dinv);
    cudaGetSymbolAddress((void**)&pdegc, d_degc);
    cudaGetSymbolAddress((void**)&prow,  d_rowptr);
    cudaGetSymbolAddress((void**)&pcur,  d_cursor);
    cudaGetSymbolAddress((void**)&pcol,  d_col);

    const int TPB = 256;
    const int eBlocks = (EE + TPB - 1) / TPB;
    const int gemmBlocks = (NN + BM - 1) / BM;

    // CSR build
    cudaMemsetAsync(pdegc, 0, NN * sizeof(int), 0);
    cudaMemsetAsync(pcur,  0, NN * sizeof(int), 0);
    count_deg_kernel<<<eBlocks, TPB>>>(ei, pdegc);
    scan_deg_kernel<<<1, 1024>>>(pdegc, prow, pdinv);
    fill_csr_kernel<<<eBlocks, TPB>>>(ei, prow, pcur, pcol);

    // pre / embedding
    sgemm_kernel<<<gemmBlocks, 256>>>(x_in, pre_w, pre_b, px, NN, FIN, 0);
    sgemm_kernel<<<gemmBlocks, 256>>>(s_in, emb_w, emb_b, ps, NN, NSE, 0);

    for (int i = 0; i < LL; i++) {
        // GIN aggregation over concat(x, s)
        gin_agg_kernel<<<NN, 256>>>(px, ps, pcol, prow, ph);
        // GCN: hs = s @ gcn_w[i]
        sgemm_kernel<<<gemmBlocks, 256>>>(ps, gcn_w + (size_t)i * HH * HH,
                                          nullptr, phs, NN, HH, 0);
        // s = tanh(norm-agg + bias)
        gcn_agg_kernel<<<NN, 128>>>(phs, pdinv, pcol, prow,
                                    gcn_b + (size_t)i * HH, ps);
        // GIN MLP
        sgemm_kernel<<<gemmBlocks, 256>>>(ph, gin_w1 + (size_t)i * 2 * HH * HH,
                                          gin_b1 + (size_t)i * HH, ph1, NN, 2 * HH, 1);
        sgemm_kernel<<<gemmBlocks, 256>>>(ph1, gin_w2 + (size_t)i * HH * HH,
                                          gin_b2 + (size_t)i * HH, px, NN, HH, 1);
    }

    // whp on concat
    concat_kernel<<<(NN * 64 + TPB - 1) / TPB, TPB>>>(px, ps, ph);
    sgemm_kernel<<<gemmBlocks, 256>>>(ph, whp_w, whp_b, ph1, NN, 2 * HH, 0);

    // pool -> post -> readout
    cudaMemsetAsync(pg, 0, GG * HH * sizeof(float), 0);
    pool_kernel<<<(NN * HH + TPB - 1) / TPB, TPB>>>(ph1, batch, pg);
    post_kernel<<<GG, HH>>>(pg, post_w, post_b, pgp);
    readout_kernel<<<1, GG>>>(pgp, ro_w, ro_b, out);
}

// round 3
// speedup vs baseline: 1.2070x; 1.2070x over previous
#include <cuda_runtime.h>
#include <cuda_bf16.h>
#include <math.h>

// Problem constants (fixed by the dataset)
#define NN 50000
#define EE 800000
#define HH 128
#define FIN 128
#define NSE 16
#define LL 3
#define CC 10
#define GG 256

// ---------------- scratch (static __device__ — no allocs allowed) ----------
__device__ float d_x [NN * HH];       // x stream
__device__ float d_s [NN * HH];       // s stream
__device__ float d_y [NN * HH];       // gin pre-agg GEMM out / whp out
__device__ float d_z [NN * HH];       // gin post-agg activation
__device__ float d_hs[NN * HH];       // s @ gcn_w
__device__ float d_g [GG * HH];       // pooled
__device__ float d_gp[GG * HH];       // post out
__device__ float d_dinv[NN];
__device__ int   d_degc[NN];
__device__ int   d_rowptr[NN + 1];
__device__ int   d_cursor[NN];
__device__ int   d_col[EE];

// ---------------- CSR build ------------------------------------------------
__global__ void count_deg_kernel(const int* __restrict__ ei, int* __restrict__ degc) {
    int e = blockIdx.x * blockDim.x + threadIdx.x;
    if (e < EE) atomicAdd(&degc[ei[EE + e]], 1);
}

// single block, 1024 threads: exclusive scan of degc -> rowptr, plus dinv
__global__ void scan_deg_kernel(const int* __restrict__ degc,
                                int* __restrict__ rowptr,
                                float* __restrict__ dinv) {
    __shared__ int ssum[1024];
    int t = threadIdx.x;
    const int chunk = (NN + 1023) / 1024;
    int b0 = t * chunk;
    int b1 = b0 + chunk; if (b1 > NN) b1 = NN;
    int sum = 0;
    for (int i = b0; i < b1; i++) sum += degc[i];
    ssum[t] = sum;
    __syncthreads();
    for (int off = 1; off < 1024; off <<= 1) {
        int v = 0;
        if (t >= off) v = ssum[t - off];
        __syncthreads();
        if (t >= off) ssum[t] += v;
        __syncthreads();
    }
    int prefix = (t == 0) ? 0 : ssum[t - 1];
    for (int i = b0; i < b1; i++) {
        int d = degc[i];
        rowptr[i] = prefix;
        prefix += d;
        dinv[i] = rsqrtf((float)d + 1.0f);
    }
    if (t == 1023) rowptr[NN] = ssum[1023];
}

__global__ void fill_csr_kernel(const int* __restrict__ ei,
                                const int* __restrict__ rowptr,
                                int* __restrict__ cursor,
                                int* __restrict__ col) {
    int e = blockIdx.x * blockDim.x + threadIdx.x;
    if (e < EE) {
        int src = ei[e];
        int dst = ei[EE + e];
        int pos = atomicAdd(&cursor[dst], 1);
        col[rowptr[dst] + pos] = src;
    }
}

// ---------------- SGEMM (double-buffered, optional dual-A for concat) ------
// C[M,128] = A1[M,K1] @ W[0:K1,:] + A2[M,K2] @ W[K1:K1+K2,:] (+bias)(+relu)
#define BM 128
#define BN 128
#define BK 8
__global__ __launch_bounds__(256)
void sgemm_dual_kernel(const float* __restrict__ A1, int K1,
                       const float* __restrict__ A2, int K2,
                       const float* __restrict__ W,
                       const float* __restrict__ bias,
                       float* __restrict__ C, int M, int relu) {
    __shared__ float As[2][BK][BM];
    __shared__ float Bs[2][BK][BN];
    const int row0 = blockIdx.x * BM;
    const int tid  = threadIdx.x;
    const int ty   = tid >> 4;           // 0..15
    const int tx   = tid & 15;           // 0..15
    const int aRow = tid >> 1;           // 0..127
    const int aK   = (tid & 1) * 4;      // 0 or 4
    const int bRow = tid >> 5;           // 0..7
    const int bCol = (tid & 31) * 4;     // 0..124
    const int nb   = (K1 + K2) / BK;

    float acc[8][8];
#pragma unroll
    for (int i = 0; i < 8; i++)
#pragma unroll
        for (int j = 0; j < 8; j++) acc[i][j] = 0.0f;

    auto loadA = [&](int kb) -> float4 {
        int kg = kb * BK + aK;
        const float* Ap; int kl, Kd;
        if (kg < K1) { Ap = A1; kl = kg; Kd = K1; }
        else         { Ap = A2; kl = kg - K1; Kd = K2; }
        if (row0 + aRow < M)
            return *(const float4*)(Ap + (size_t)(row0 + aRow) * Kd + kl);
        return make_float4(0.f, 0.f, 0.f, 0.f);
    };
    auto loadB = [&](int kb) -> float4 {
        return *(const float4*)(W + (size_t)(kb * BK + bRow) * BN + bCol);
    };

    float4 av = loadA(0);
    float4 bv = loadB(0);
    As[0][aK + 0][aRow] = av.x; As[0][aK + 1][aRow] = av.y;
    As[0][aK + 2][aRow] = av.z; As[0][aK + 3][aRow] = av.w;
    *(float4*)&Bs[0][bRow][bCol] = bv;
    __syncthreads();

    for (int kb = 0; kb < nb; kb++) {
        const int cur = kb & 1, nxt = cur ^ 1;
        if (kb + 1 < nb) { av = loadA(kb + 1); bv = loadB(kb + 1); }
#pragma unroll
        for (int kk = 0; kk < BK; kk++) {
            float4 a0 = *(float4*)&As[cur][kk][ty * 8];
            float4 a1 = *(float4*)&As[cur][kk][ty * 8 + 4];
            float4 b0 = *(float4*)&Bs[cur][kk][tx * 8];
            float4 b1 = *(float4*)&Bs[cur][kk][tx * 8 + 4];
            float ra[8] = {a0.x, a0.y, a0.z, a0.w, a1.x, a1.y, a1.z, a1.w};
            float rb[8] = {b0.x, b0.y, b0.z, b0.w, b1.x, b1.y, b1.z, b1.w};
#pragma unroll
            for (int i = 0; i < 8; i++)
#pragma unroll
                for (int j = 0; j < 8; j++)
                    acc[i][j] = fmaf(ra[i], rb[j], acc[i][j]);
        }
        if (kb + 1 < nb) {
            As[nxt][aK + 0][aRow] = av.x; As[nxt][aK + 1][aRow] = av.y;
            As[nxt][aK + 2][aRow] = av.z; As[nxt][aK + 3][aRow] = av.w;
            *(float4*)&Bs[nxt][bRow][bCol] = bv;
        }
        __syncthreads();
    }

#pragma unroll
    for (int i = 0; i < 8; i++) {
        int row = row0 + ty * 8 + i;
        if (row < M) {
#pragma unroll
            for (int j = 0; j < 8; j++) {
                int colc = tx * 8 + j;
                float v = acc[i][j];
                if (bias) v += bias[colc];
                if (relu) v = fmaxf(v, 0.0f);
                C[(size_t)row * BN + colc] = v;
            }
        }
    }
}

// ---------------- GIN fused agg: z = relu(y_i + sum_in y_src + b1) ---------
// warp per node, float4 per lane (128 features). (A·X)W == A·(XW) algebra.
__global__ __launch_bounds__(256)
void gin_agg_relu_kernel(const float* __restrict__ y,
                         const int* __restrict__ col,
                         const int* __restrict__ rowptr,
                         const float* __restrict__ b1,
                         float* __restrict__ z) {
    int warp = (blockIdx.x * blockDim.x + threadIdx.x) >> 5;
    if (warp >= NN) return;
    int lane = threadIdx.x & 31;
    const float4* yv = (const float4*)y;
    float4 a = yv[(size_t)warp * 32 + lane];
    float ax = a.x, ay = a.y, az = a.z, aw = a.w;
    int b = rowptr[warp], e = rowptr[warp + 1];
    int j = b;
    for (; j + 4 <= e; j += 4) {
        int s0 = col[j], s1 = col[j + 1], s2 = col[j + 2], s3 = col[j + 3];
        float4 v0 = yv[(size_t)s0 * 32 + lane];
        float4 v1 = yv[(size_t)s1 * 32 + lane];
        float4 v2 = yv[(size_t)s2 * 32 + lane];
        float4 v3 = yv[(size_t)s3 * 32 + lane];
        ax += v0.x + v1.x + v2.x + v3.x;
        ay += v0.y + v1.y + v2.y + v3.y;
        az += v0.z + v1.z + v2.z + v3.z;
        aw += v0.w + v1.w + v2.w + v3.w;
    }
    for (; j < e; j++) {
        float4 v = yv[(size_t)col[j] * 32 + lane];
        ax += v.x; ay += v.y; az += v.z; aw += v.w;
    }
    float4 bb = ((const float4*)b1)[lane];
    float4 o;
    o.x = fmaxf(ax + bb.x, 0.f);
    o.y = fmaxf(ay + bb.y, 0.f);
    o.z = fmaxf(az + bb.z, 0.f);
    o.w = fmaxf(aw + bb.w, 0.f);
    ((float4*)z)[(size_t)warp * 32 + lane] = o;
}

// ---------------- GCN agg: s = tanh(di*sum dinv_j*hs_j + hs_i*di^2 + b) ----
__global__ __launch_bounds__(256)
void gcn_agg_kernel(const float* __restrict__ hs,
                    const float* __restrict__ dinv,
                    const int* __restrict__ col,
                    const int* __restrict__ rowptr,
                    const float* __restrict__ bias,
                    float* __restrict__ s) {
    int warp = (blockIdx.x * blockDim.x + threadIdx.x) >> 5;
    if (warp >= NN) return;
    int lane = threadIdx.x & 31;
    const float4* hv = (const float4*)hs;
    float ax = 0.f, ay = 0.f, az = 0.f, aw = 0.f;
    int b = rowptr[warp], e = rowptr[warp + 1];
    int j = b;
    for (; j + 4 <= e; j += 4) {
        int s0 = col[j], s1 = col[j + 1], s2 = col[j + 2], s3 = col[j + 3];
        float d0 = dinv[s0], d1 = dinv[s1], d2 = dinv[s2], d3 = dinv[s3];
        float4 v0 = hv[(size_t)s0 * 32 + lane];
        float4 v1 = hv[(size_t)s1 * 32 + lane];
        float4 v2 = hv[(size_t)s2 * 32 + lane];
        float4 v3 = hv[(size_t)s3 * 32 + lane];
        ax += d0 * v0.x + d1 * v1.x + d2 * v2.x + d3 * v3.x;
        ay += d0 * v0.y + d1 * v1.y + d2 * v2.y + d3 * v3.y;
        az += d0 * v0.z + d1 * v1.z + d2 * v2.z + d3 * v3.z;
        aw += d0 * v0.w + d1 * v1.w + d2 * v2.w + d3 * v3.w;
    }
    for (; j < e; j++) {
        int sc = col[j];
        float dd = dinv[sc];
        float4 v = hv[(size_t)sc * 32 + lane];
        ax += dd * v.x; ay += dd * v.y; az += dd * v.z; aw += dd * v.w;
    }
    float di = dinv[warp];
    float di2 = di * di;
    float4 hself = hv[(size_t)warp * 32 + lane];
    float4 bb = ((const float4*)bias)[lane];
    float4 o;
    o.x = tanhf(di * ax + hself.x * di2 + bb.x);
    o.y = tanhf(di * ay + hself.y * di2 + bb.y);
    o.z = tanhf(di * az + hself.z * di2 + bb.z);
    o.w = tanhf(di * aw + hself.w * di2 + bb.w);
    ((float4*)s)[(size_t)warp * 32 + lane] = o;
}

// ---------------- global add pool -----------------------------------------
__global__ void pool_kernel(const float* __restrict__ xf,
                            const int* __restrict__ batch,
                            float* __restrict__ g) {
    int idx = blockIdx.x * blockDim.x + threadIdx.x;   // N*H
    if (idx < NN * HH) {
        int i = idx >> 7;
        int f = idx & 127;
        atomicAdd(&g[batch[i] * HH + f], xf[idx]);
    }
}

// ---------------- post: relu(g @ post_w + b) ------------------------------
__global__ void post_kernel(const float* __restrict__ g,
                            const float* __restrict__ W,
                            const float* __restrict__ bias,
                            float* __restrict__ gp) {
    int r = blockIdx.x;       // 0..255
    int c = threadIdx.x;      // 0..127
    __shared__ float row[HH];
    row[c] = g[(size_t)r * HH + c];
    __syncthreads();
    float acc = bias[c];
#pragma unroll 8
    for (int k = 0; k < HH; k++) acc = fmaf(row[k], W[(size_t)k * HH + c], acc);
    gp[(size_t)r * HH + c] = fmaxf(acc, 0.0f);
}

// ---------------- readout + log_softmax ----------------------------------
__global__ void readout_kernel(const float* __restrict__ gp,
                               const float* __restrict__ W,
                               const float* __restrict__ bias,
                               float* __restrict__ out) {
    int r = blockIdx.x * blockDim.x + threadIdx.x;
    if (r < GG) {
        float logit[CC];
#pragma unroll
        for (int c = 0; c < CC; c++) logit[c] = bias[c];
        for (int k = 0; k < HH; k++) {
            float gv = gp[(size_t)r * HH + k];
#pragma unroll
            for (int c = 0; c < CC; c++)
                logit[c] = fmaf(gv, W[(size_t)k * CC + c], logit[c]);
        }
        float m = logit[0];
#pragma unroll
        for (int c = 1; c < CC; c++) m = fmaxf(m, logit[c]);
        float sum = 0.0f;
#pragma unroll
        for (int c = 0; c < CC; c++) sum += expf(logit[c] - m);
        float lse = m + logf(sum);
#pragma unroll
        for (int c = 0; c < CC; c++) out[(size_t)r * CC + c] = logit[c] - lse;
    }
}

// ---------------- driver ---------------------------------------------------
extern "C" void kernel_launch(void* const* d_in, const int* in_sizes, int n_in,
                              void* d_out, int out_size) {
    const float* x_in   = (const float*)d_in[0];
    const float* s_in   = (const float*)d_in[1];
    const int*   ei     = (const int*)d_in[2];
    const int*   batch  = (const int*)d_in[3];
    const float* pre_w  = (const float*)d_in[4];
    const float* pre_b  = (const float*)d_in[5];
    const float* emb_w  = (const float*)d_in[6];
    const float* emb_b  = (const float*)d_in[7];
    const float* gin_w1 = (const float*)d_in[8];
    const float* gin_b1 = (const float*)d_in[9];
    const float* gin_w2 = (const float*)d_in[10];
    const float* gin_b2 = (const float*)d_in[11];
    const float* gcn_w  = (const float*)d_in[12];
    const float* gcn_b  = (const float*)d_in[13];
    const float* whp_w  = (const float*)d_in[14];
    const float* whp_b  = (const float*)d_in[15];
    const float* post_w = (const float*)d_in[16];
    const float* post_b = (const float*)d_in[17];
    const float* ro_w   = (const float*)d_in[18];
    const float* ro_b   = (const float*)d_in[19];
    float* out = (float*)d_out;

    float *px, *ps, *py, *pz, *phs, *pg, *pgp, *pdinv;
    int *pdegc, *prow, *pcur, *pcol;
    cudaGetSymbolAddress((void**)&px,    d_x);
    cudaGetSymbolAddress((void**)&ps,    d_s);
    cudaGetSymbolAddress((void**)&py,    d_y);
    cudaGetSymbolAddress((void**)&pz,    d_z);
    cudaGetSymbolAddress((void**)&phs,   d_hs);
    cudaGetSymbolAddress((void**)&pg,    d_g);
    cudaGetSymbolAddress((void**)&pgp,   d_gp);
    cudaGetSymbolAddress((void**)&pdinv, d_dinv);
    cudaGetSymbolAddress((void**)&pdegc, d_degc);
    cudaGetSymbolAddress((void**)&prow,  d_rowptr);
    cudaGetSymbolAddress((void**)&pcur,  d_cursor);
    cudaGetSymbolAddress((void**)&pcol,  d_col);

    const int TPB = 256;
    const int eBlocks = (EE + TPB - 1) / TPB;
    const int gemmBlocks = (NN + BM - 1) / BM;
    const int aggBlocks = (NN * 32 + TPB - 1) / TPB;

    // CSR build
    cudaMemsetAsync(pdegc, 0, NN * sizeof(int), 0);
    cudaMemsetAsync(pcur,  0, NN * sizeof(int), 0);
    count_deg_kernel<<<eBlocks, TPB>>>(ei, pdegc);
    scan_deg_kernel<<<1, 1024>>>(pdegc, prow, pdinv);
    fill_csr_kernel<<<eBlocks, TPB>>>(ei, prow, pcur, pcol);

    // pre / embedding
    sgemm_dual_kernel<<<gemmBlocks, 256>>>(x_in, FIN, nullptr, 0, pre_w, pre_b, px, NN, 0);
    sgemm_dual_kernel<<<gemmBlocks, 256>>>(s_in, NSE, nullptr, 0, emb_w, emb_b, ps, NN, 0);

    for (int i = 0; i < LL; i++) {
        // y = [x|s] @ gin_w1  (split dual-A GEMM, no concat materialized)
        sgemm_dual_kernel<<<gemmBlocks, 256>>>(px, HH, ps, HH,
                                               gin_w1 + (size_t)i * 2 * HH * HH,
                                               nullptr, py, NN, 0);
        // hs = s @ gcn_w[i]
        sgemm_dual_kernel<<<gemmBlocks, 256>>>(ps, HH, nullptr, 0,
                                               gcn_w + (size_t)i * HH * HH,
                                               nullptr, phs, NN, 0);
        // z = relu(y + A·y + b1)   [(X+AX)W == Y+AY]
        gin_agg_relu_kernel<<<aggBlocks, TPB>>>(py, pcol, prow,
                                                gin_b1 + (size_t)i * HH, pz);
        // s = tanh(norm-agg(hs) + b)
        gcn_agg_kernel<<<aggBlocks, TPB>>>(phs, pdinv, pcol, prow,
                                           gcn_b + (size_t)i * HH, ps);
        // x = relu(z @ gin_w2 + b2)
        sgemm_dual_kernel<<<gemmBlocks, 256>>>(pz, HH, nullptr, 0,
                                               gin_w2 + (size_t)i * HH * HH,
                                               gin_b2 + (size_t)i * HH, px, NN, 1);
    }

    // whp on split concat
    sgemm_dual_kernel<<<gemmBlocks, 256>>>(px, HH, ps, HH, whp_w, whp_b, py, NN, 0);

    // pool -> post -> readout
    cudaMemsetAsync(pg, 0, GG * HH * sizeof(float), 0);
    pool_kernel<<<(NN * HH + TPB - 1) / TPB, TPB>>>(py, batch, pg);
    post_kernel<<<GG, HH>>>(pg, post_w, post_b, pgp);
    readout_kernel<<<1, GG>>>(pgp, ro_w, ro_b, out);
}

// round 5
// speedup vs baseline: 2.0098x; 1.6651x over previous
#include <cuda_runtime.h>
#include <cuda_bf16.h>
#include <math.h>
#include <stdint.h>

// Problem constants (fixed by the dataset)
#define NN 50000
#define EE 800000
#define HH 128
#define FIN 128
#define NSE 16
#define LL 3
#define CC 10
#define GG 256

// ---------------- scratch (static __device__ — no allocs allowed) ----------
__device__ float d_x [NN * HH];
__device__ float d_s [NN * HH];
__device__ float d_y [NN * HH];
__device__ float d_z [NN * HH];
__device__ float d_hs[NN * HH];
__device__ float d_g [GG * HH];
__device__ float d_gp[GG * HH];
__device__ float d_dinv[NN];
__device__ int   d_degc[NN];
__device__ int   d_rowptr[NN + 1];
__device__ int   d_cursor[NN];
__device__ int   d_col[EE];

// ---------------- CSR build ------------------------------------------------
__global__ void count_deg_kernel(const int* __restrict__ ei, int* __restrict__ degc) {
    int e = blockIdx.x * blockDim.x + threadIdx.x;
    if (e < EE) atomicAdd(&degc[ei[EE + e]], 1);
}

__global__ void scan_deg_kernel(const int* __restrict__ degc,
                                int* __restrict__ rowptr,
                                float* __restrict__ dinv) {
    __shared__ int ssum[1024];
    int t = threadIdx.x;
    const int chunk = (NN + 1023) / 1024;
    int b0 = t * chunk;
    int b1 = b0 + chunk; if (b1 > NN) b1 = NN;
    int sum = 0;
    for (int i = b0; i < b1; i++) sum += degc[i];
    ssum[t] = sum;
    __syncthreads();
    for (int off = 1; off < 1024; off <<= 1) {
        int v = 0;
        if (t >= off) v = ssum[t - off];
        __syncthreads();
        if (t >= off) ssum[t] += v;
        __syncthreads();
    }
    int prefix = (t == 0) ? 0 : ssum[t - 1];
    for (int i = b0; i < b1; i++) {
        int d = degc[i];
        rowptr[i] = prefix;
        prefix += d;
        dinv[i] = rsqrtf((float)d + 1.0f);
    }
    if (t == 1023) rowptr[NN] = ssum[1023];
}

__global__ void fill_csr_kernel(const int* __restrict__ ei,
                                const int* __restrict__ rowptr,
                                int* __restrict__ cursor,
                                int* __restrict__ col) {
    int e = blockIdx.x * blockDim.x + threadIdx.x;
    if (e < EE) {
        int src = ei[e];
        int dst = ei[EE + e];
        int pos = atomicAdd(&cursor[dst], 1);
        col[rowptr[dst] + pos] = src;
    }
}

// ---------------- TF32 helpers ---------------------------------------------
__device__ __forceinline__ uint32_t f2tf32(float x) {
    uint32_t r;
    asm("cvt.rna.tf32.f32 %0, %1;" : "=r"(r) : "f"(x));
    return r;
}
__device__ __forceinline__ void split_tf32(float x, uint32_t& hi, uint32_t& lo) {
    hi = f2tf32(x);
    lo = f2tf32(x - __uint_as_float(hi));
}
__device__ __forceinline__ void mma_tf32(float* c, const uint32_t* a, const uint32_t* b) {
    asm volatile("mma.sync.aligned.m16n8k8.row.col.f32.tf32.tf32.f32 "
        "{%0,%1,%2,%3}, {%4,%5,%6,%7}, {%8,%9}, {%0,%1,%2,%3};"
        : "+f"(c[0]), "+f"(c[1]), "+f"(c[2]), "+f"(c[3])
        : "r"(a[0]), "r"(a[1]), "r"(a[2]), "r"(a[3]), "r"(b[0]), "r"(b[1]));
}

// ---------------- TF32 GEMM (split-precision, dual-A) ----------------------
// C[M,128] = A1[M,K1] @ W[0:K1,:] + A2[M,K2] @ W[K1:,:] (+bias)(+relu)
// Block 128x128, BK=16, 8 warps as 4(M)x2(N); warp tile 32x64.
#define TM 128
#define TN 128
#define TKK 16
__global__ __launch_bounds__(256)
void tf32_gemm_dual(const float* __restrict__ A1, int K1,
                    const float* __restrict__ A2, int K2,
                    const float* __restrict__ W,
                    const float* __restrict__ bias,
                    float* __restrict__ C, int M, int relu) {
    __shared__ float As[2][TM][TKK + 4];
    __shared__ float Bs[2][TKK][TN + 4];
    const int tid  = threadIdx.x;
    const int wid  = tid >> 5;
    const int lane = tid & 31;
    const int g    = lane >> 2;      // 0..7
    const int t    = lane & 3;       // 0..3
    const int wm   = wid & 3;        // M warp coord (0..3)
    const int wn   = wid >> 2;       // N warp coord (0..1)
    const int row0 = blockIdx.x * TM;
    const int nb   = (K1 + K2) / TKK;

    float acc[2][8][4];
#pragma unroll
    for (int mi = 0; mi < 2; mi++)
#pragma unroll
        for (int ni = 0; ni < 8; ni++)
#pragma unroll
            for (int q = 0; q < 4; q++) acc[mi][ni][q] = 0.0f;

    auto fetchA = [&](int kb, int s) -> float4 {
        int r = s >> 2, c4 = (s & 3) * 4;
        int kg = kb * TKK + c4;
        const float* Ap; int kl, Kd;
        if (kg < K1) { Ap = A1; kl = kg; Kd = K1; }
        else         { Ap = A2; kl = kg - K1; Kd = K2; }
        if (row0 + r < M)
            return *(const float4*)(Ap + (size_t)(row0 + r) * Kd + kl);
        return make_float4(0.f, 0.f, 0.f, 0.f);
    };
    auto fetchB = [&](int kb, int s) -> float4 {
        int kr = s >> 5, cn = (s & 31) * 4;
        return *(const float4*)(W + (size_t)(kb * TKK + kr) * TN + cn);
    };
    auto stA = [&](int buf, int s, float4 v) {
        int r = s >> 2, c = (s & 3) * 4;
        *(float4*)&As[buf][r][c] = v;
    };
    auto stB = [&](int buf, int s, float4 v) {
        int kr = s >> 5, cn = (s & 31) * 4;
        *(float4*)&Bs[buf][kr][cn] = v;
    };

    stA(0, tid, fetchA(0, tid));
    stA(0, tid + 256, fetchA(0, tid + 256));
    stB(0, tid, fetchB(0, tid));
    stB(0, tid + 256, fetchB(0, tid + 256));
    __syncthreads();

    for (int kb = 0; kb < nb; kb++) {
        const int cur = kb & 1, nxt = cur ^ 1;
        float4 pa0, pa1, pb0, pb1;
        if (kb + 1 < nb) {
            pa0 = fetchA(kb + 1, tid);
            pa1 = fetchA(kb + 1, tid + 256);
            pb0 = fetchB(kb + 1, tid);
            pb1 = fetchB(kb + 1, tid + 256);
        }
#pragma unroll
        for (int ks = 0; ks < 2; ks++) {
            const int k0 = ks * 8;
            uint32_t ahi[2][4], alo[2][4];
#pragma unroll
            for (int mi = 0; mi < 2; mi++) {
                int mb = wm * 32 + mi * 16;
                split_tf32(As[cur][mb + g    ][k0 + t    ], ahi[mi][0], alo[mi][0]);
                split_tf32(As[cur][mb + g + 8][k0 + t    ], ahi[mi][1], alo[mi][1]);
                split_tf32(As[cur][mb + g    ][k0 + t + 4], ahi[mi][2], alo[mi][2]);
                split_tf32(As[cur][mb + g + 8][k0 + t + 4], ahi[mi][3], alo[mi][3]);
            }
            uint32_t bhi[8][2], blo[8][2];
#pragma unroll
            for (int ni = 0; ni < 8; ni++) {
                int nbase = wn * 64 + ni * 8 + g;
                split_tf32(Bs[cur][k0 + t    ][nbase], bhi[ni][0], blo[ni][0]);
                split_tf32(Bs[cur][k0 + t + 4][nbase], bhi[ni][1], blo[ni][1]);
            }
#pragma unroll
            for (int mi = 0; mi < 2; mi++)
#pragma unroll
                for (int ni = 0; ni < 8; ni++) {
                    mma_tf32(acc[mi][ni], ahi[mi], bhi[ni]);
                    mma_tf32(acc[mi][ni], ahi[mi], blo[ni]);
                    mma_tf32(acc[mi][ni], alo[mi], bhi[ni]);
                }
        }
        if (kb + 1 < nb) {
            stA(nxt, tid, pa0);
            stA(nxt, tid + 256, pa1);
            stB(nxt, tid, pb0);
            stB(nxt, tid + 256, pb1);
        }
        __syncthreads();
    }

    // Epilogue: c0->(g,2t) c1->(g,2t+1) c2->(g+8,2t) c3->(g+8,2t+1)
#pragma unroll
    for (int mi = 0; mi < 2; mi++) {
        int rbase = row0 + wm * 32 + mi * 16 + g;
#pragma unroll
        for (int ni = 0; ni < 8; ni++) {
            int colb = wn * 64 + ni * 8 + 2 * t;
            float b0 = bias ? bias[colb]     : 0.f;
            float b1 = bias ? bias[colb + 1] : 0.f;
            float v0 = acc[mi][ni][0] + b0;
            float v1 = acc[mi][ni][1] + b1;
            float v2 = acc[mi][ni][2] + b0;
            float v3 = acc[mi][ni][3] + b1;
            if (relu) {
                v0 = fmaxf(v0, 0.f); v1 = fmaxf(v1, 0.f);
                v2 = fmaxf(v2, 0.f); v3 = fmaxf(v3, 0.f);
            }
            if (rbase < M)
                *(float2*)(C + (size_t)rbase * TN + colb) = make_float2(v0, v1);
            if (rbase + 8 < M)
                *(float2*)(C + (size_t)(rbase + 8) * TN + colb) = make_float2(v2, v3);
        }
    }
}

// ---------------- GIN fused agg: z = relu(y_i + sum_in y_src + b1) ---------
__global__ __launch_bounds__(256)
void gin_agg_relu_kernel(const float* __restrict__ y,
                         const int* __restrict__ col,
                         const int* __restrict__ rowptr,
                         const float* __restrict__ b1,
                         float* __restrict__ z) {
    int warp = (blockIdx.x * blockDim.x + threadIdx.x) >> 5;
    if (warp >= NN) return;
    int lane = threadIdx.x & 31;
    const float4* yv = (const float4*)y;
    float4 a = yv[(size_t)warp * 32 + lane];
    float ax = a.x, ay = a.y, az = a.z, aw = a.w;
    int b = rowptr[warp], e = rowptr[warp + 1];
    int j = b;
    for (; j + 4 <= e; j += 4) {
        int s0 = col[j], s1 = col[j + 1], s2 = col[j + 2], s3 = col[j + 3];
        float4 v0 = yv[(size_t)s0 * 32 + lane];
        float4 v1 = yv[(size_t)s1 * 32 + lane];
        float4 v2 = yv[(size_t)s2 * 32 + lane];
        float4 v3 = yv[(size_t)s3 * 32 + lane];
        ax += v0.x + v1.x + v2.x + v3.x;
        ay += v0.y + v1.y + v2.y + v3.y;
        az += v0.z + v1.z + v2.z + v3.z;
        aw += v0.w + v1.w + v2.w + v3.w;
    }
    for (; j < e; j++) {
        float4 v = yv[(size_t)col[j] * 32 + lane];
        ax += v.x; ay += v.y; az += v.z; aw += v.w;
    }
    float4 bb = ((const float4*)b1)[lane];
    float4 o;
    o.x = fmaxf(ax + bb.x, 0.f);
    o.y = fmaxf(ay + bb.y, 0.f);
    o.z = fmaxf(az + bb.z, 0.f);
    o.w = fmaxf(aw + bb.w, 0.f);
    ((float4*)z)[(size_t)warp * 32 + lane] = o;
}

// ---------------- GCN agg ---------------------------------------------------
__global__ __launch_bounds__(256)
void gcn_agg_kernel(const float* __restrict__ hs,
                    const float* __restrict__ dinv,
                    const int* __restrict__ col,
                    const int* __restrict__ rowptr,
                    const float* __restrict__ bias,
                    float* __restrict__ s) {
    int warp = (blockIdx.x * blockDim.x + threadIdx.x) >> 5;
    if (warp >= NN) return;
    int lane = threadIdx.x & 31;
    const float4* hv = (const float4*)hs;
    float ax = 0.f, ay = 0.f, az = 0.f, aw = 0.f;
    int b = rowptr[warp], e = rowptr[warp + 1];
    int j = b;
    for (; j + 4 <= e; j += 4) {
        int s0 = col[j], s1 = col[j + 1], s2 = col[j + 2], s3 = col[j + 3];
        float d0 = dinv[s0], d1 = dinv[s1], d2 = dinv[s2], d3 = dinv[s3];
        float4 v0 = hv[(size_t)s0 * 32 + lane];
        float4 v1 = hv[(size_t)s1 * 32 + lane];
        float4 v2 = hv[(size_t)s2 * 32 + lane];
        float4 v3 = hv[(size_t)s3 * 32 + lane];
        ax += d0 * v0.x + d1 * v1.x + d2 * v2.x + d3 * v3.x;
        ay += d0 * v0.y + d1 * v1.y + d2 * v2.y + d3 * v3.y;
        az += d0 * v0.z + d1 * v1.z + d2 * v2.z + d3 * v3.z;
        aw += d0 * v0.w + d1 * v1.w + d2 * v2.w + d3 * v3.w;
    }
    for (; j < e; j++) {
        int sc = col[j];
        float dd = dinv[sc];
        float4 v = hv[(size_t)sc * 32 + lane];
        ax += dd * v.x; ay += dd * v.y; az += dd * v.z; aw += dd * v.w;
    }
    float di = dinv[warp];
    float di2 = di * di;
    float4 hself = hv[(size_t)warp * 32 + lane];
    float4 bb = ((const float4*)bias)[lane];
    float4 o;
    o.x = tanhf(di * ax + hself.x * di2 + bb.x);
    o.y = tanhf(di * ay + hself.y * di2 + bb.y);
    o.z = tanhf(di * az + hself.z * di2 + bb.z);
    o.w = tanhf(di * aw + hself.w * di2 + bb.w);
    ((float4*)s)[(size_t)warp * 32 + lane] = o;
}

// ---------------- global add pool -----------------------------------------
__global__ void pool_kernel(const float* __restrict__ xf,
                            const int* __restrict__ batch,
                            float* __restrict__ g) {
    int idx = blockIdx.x * blockDim.x + threadIdx.x;
    if (idx < NN * HH) {
        int i = idx >> 7;
        int f = idx & 127;
        atomicAdd(&g[batch[i] * HH + f], xf[idx]);
    }
}

// ---------------- post: relu(g @ post_w + b) ------------------------------
__global__ void post_kernel(const float* __restrict__ g,
                            const float* __restrict__ W,
                            const float* __restrict__ bias,
                            float* __restrict__ gp) {
    int r = blockIdx.x;
    int c = threadIdx.x;
    __shared__ float row[HH];
    row[c] = g[(size_t)r * HH + c];
    __syncthreads();
    float acc = bias[c];
#pragma unroll 8
    for (int k = 0; k < HH; k++) acc = fmaf(row[k], W[(size_t)k * HH + c], acc);
    gp[(size_t)r * HH + c] = fmaxf(acc, 0.0f);
}

// ---------------- readout + log_softmax ----------------------------------
__global__ void readout_kernel(const float* __restrict__ gp,
                               const float* __restrict__ W,
                               const float* __restrict__ bias,
                               float* __restrict__ out) {
    int r = blockIdx.x * blockDim.x + threadIdx.x;
    if (r < GG) {
        float logit[CC];
#pragma unroll
        for (int c = 0; c < CC; c++) logit[c] = bias[c];
        for (int k = 0; k < HH; k++) {
            float gv = gp[(size_t)r * HH + k];
#pragma unroll
            for (int c = 0; c < CC; c++)
                logit[c] = fmaf(gv, W[(size_t)k * CC + c], logit[c]);
        }
        float m = logit[0];
#pragma unroll
        for (int c = 1; c < CC; c++) m = fmaxf(m, logit[c]);
        float sum = 0.0f;
#pragma unroll
        for (int c = 0; c < CC; c++) sum += expf(logit[c] - m);
        float lse = m + logf(sum);
#pragma unroll
        for (int c = 0; c < CC; c++) out[(size_t)r * CC + c] = logit[c] - lse;
    }
}

// ---------------- driver ---------------------------------------------------
extern "C" void kernel_launch(void* const* d_in, const int* in_sizes, int n_in,
                              void* d_out, int out_size) {
    const float* x_in   = (const float*)d_in[0];
    const float* s_in   = (const float*)d_in[1];
    const int*   ei     = (const int*)d_in[2];
    const int*   batch  = (const int*)d_in[3];
    const float* pre_w  = (const float*)d_in[4];
    const float* pre_b  = (const float*)d_in[5];
    const float* emb_w  = (const float*)d_in[6];
    const float* emb_b  = (const float*)d_in[7];
    const float* gin_w1 = (const float*)d_in[8];
    const float* gin_b1 = (const float*)d_in[9];
    const float* gin_w2 = (const float*)d_in[10];
    const float* gin_b2 = (const float*)d_in[11];
    const float* gcn_w  = (const float*)d_in[12];
    const float* gcn_b  = (const float*)d_in[13];
    const float* whp_w  = (const float*)d_in[14];
    const float* whp_b  = (const float*)d_in[15];
    const float* post_w = (const float*)d_in[16];
    const float* post_b = (const float*)d_in[17];
    const float* ro_w   = (const float*)d_in[18];
    const float* ro_b   = (const float*)d_in[19];
    float* out = (float*)d_out;

    float *px, *ps, *py, *pz, *phs, *pg, *pgp, *pdinv;
    int *pdegc, *prow, *pcur, *pcol;
    cudaGetSymbolAddress((void**)&px,    d_x);
    cudaGetSymbolAddress((void**)&ps,    d_s);
    cudaGetSymbolAddress((void**)&py,    d_y);
    cudaGetSymbolAddress((void**)&pz,    d_z);
    cudaGetSymbolAddress((void**)&phs,   d_hs);
    cudaGetSymbolAddress((void**)&pg,    d_g);
    cudaGetSymbolAddress((void**)&pgp,   d_gp);
    cudaGetSymbolAddress((void**)&pdinv, d_dinv);
    cudaGetSymbolAddress((void**)&pdegc, d_degc);
    cudaGetSymbolAddress((void**)&prow,  d_rowptr);
    cudaGetSymbolAddress((void**)&pcur,  d_cursor);
    cudaGetSymbolAddress((void**)&pcol,  d_col);

    const int TPB = 256;
    const int eBlocks = (EE + TPB - 1) / TPB;
    const int gemmBlocks = (NN + TM - 1) / TM;
    const int aggBlocks = (NN * 32 + TPB - 1) / TPB;

    // CSR build
    cudaMemsetAsync(pdegc, 0, NN * sizeof(int), 0);
    cudaMemsetAsync(pcur,  0, NN * sizeof(int), 0);
    count_deg_kernel<<<eBlocks, TPB>>>(ei, pdegc);
    scan_deg_kernel<<<1, 1024>>>(pdegc, prow, pdinv);
    fill_csr_kernel<<<eBlocks, TPB>>>(ei, prow, pcur, pcol);

    // pre / embedding
    tf32_gemm_dual<<<gemmBlocks, 256>>>(x_in, FIN, nullptr, 0, pre_w, pre_b, px, NN, 0);
    tf32_gemm_dual<<<gemmBlocks, 256>>>(s_in, NSE, nullptr, 0, emb_w, emb_b, ps, NN, 0);

    for (int i = 0; i < LL; i++) {
        // y = [x|s] @ gin_w1 (split dual-A)
        tf32_gemm_dual<<<gemmBlocks, 256>>>(px, HH, ps, HH,
                                            gin_w1 + (size_t)i * 2 * HH * HH,
                                            nullptr, py, NN, 0);
        // hs = s @ gcn_w[i]
        tf32_gemm_dual<<<gemmBlocks, 256>>>(ps, HH, nullptr, 0,
                                            gcn_w + (size_t)i * HH * HH,
                                            nullptr, phs, NN, 0);
        // z = relu(y + A·y + b1)
        gin_agg_relu_kernel<<<aggBlocks, TPB>>>(py, pcol, prow,
                                                gin_b1 + (size_t)i * HH, pz);
        // s = tanh(norm-agg(hs) + b)
        gcn_agg_kernel<<<aggBlocks, TPB>>>(phs, pdinv, pcol, prow,
                                           gcn_b + (size_t)i * HH, ps);
        // x = relu(z @ gin_w2 + b2)
        tf32_gemm_dual<<<gemmBlocks, 256>>>(pz, HH, nullptr, 0,
                                            gin_w2 + (size_t)i * HH * HH,
                                            gin_b2 + (size_t)i * HH, px, NN, 1);
    }

    // whp on split concat
    tf32_gemm_dual<<<gemmBlocks, 256>>>(px, HH, ps, HH, whp_w, whp_b, py, NN, 0);

    // pool -> post -> readout
    cudaMemsetAsync(pg, 0, GG * HH * sizeof(float), 0);
    pool_kernel<<<(NN * HH + TPB - 1) / TPB, TPB>>>(py, batch, pg);
    post_kernel<<<GG, HH>>>(pg, post_w, post_b, pgp);
    readout_kernel<<<1, GG>>>(pgp, ro_w, ro_b, out);
}